// round 1
// baseline (speedup 1.0000x reference)
#include <cuda_runtime.h>
#include <cstdint>

#define NTOK   8192
#define DDIM   2048
#define HDIM   2048
#define ODIM   2048
#define NEXP   8
#define CAPACITY 2560
#define ROWS_MAX 4096
#define RB_PER_E (ROWS_MAX/128)   // 32 row-blocks per expert

// ---------------- device scratch (no allocs allowed) ----------------
__device__ int   g_count[NEXP];
__device__ float g_probSum[NEXP];
__device__ int   g_tok[NEXP*NTOK];
__device__ float g_wgt[NEXP*NTOK];
__device__ int   g_pos[NEXP*NTOK];
__device__ unsigned char g_drop[NEXP*NTOK];
__device__ float g_hbuf[(size_t)NEXP*ROWS_MAX*HDIM];   // 268 MB scratch

// ---------------- init: out = x (residual), zero counters ----------------
__global__ void init_kernel(const float* __restrict__ x, float* __restrict__ out){
  if (blockIdx.x == 0 && threadIdx.x < NEXP){
    g_count[threadIdx.x] = 0;
    g_probSum[threadIdx.x] = 0.f;
  }
  size_t i = (size_t)blockIdx.x*blockDim.x + threadIdx.x;
  size_t total4 = (size_t)NTOK*ODIM/4;
  const float4* xs = reinterpret_cast<const float4*>(x);
  float4* o = reinterpret_cast<float4*>(out);
  size_t stride = (size_t)gridDim.x*blockDim.x;
  for (size_t j=i; j<total4; j+=stride) o[j] = xs[j];
}

// ---------------- router: warp per token ----------------
__global__ void router_kernel(const float* __restrict__ x, const float* __restrict__ gw,
                              const float* __restrict__ gb, const float* __restrict__ temp){
  int gwarp = (int)((blockIdx.x*blockDim.x + threadIdx.x) >> 5);
  int lane = threadIdx.x & 31;
  if (gwarp >= NTOK) return;
  const float* xr = x + (size_t)gwarp * DDIM;
  float acc[8] = {0.f,0.f,0.f,0.f,0.f,0.f,0.f,0.f};
  for (int d = lane; d < DDIM; d += 32){
    float xv = xr[d];
    const float4* g4 = reinterpret_cast<const float4*>(gw + (size_t)d*NEXP);
    float4 ga = g4[0], gbv = g4[1];
    acc[0] += xv*ga.x;  acc[1] += xv*ga.y;  acc[2] += xv*ga.z;  acc[3] += xv*ga.w;
    acc[4] += xv*gbv.x; acc[5] += xv*gbv.y; acc[6] += xv*gbv.z; acc[7] += xv*gbv.w;
  }
  #pragma unroll
  for (int off=16; off; off>>=1){
    #pragma unroll
    for (int e=0;e<8;e++) acc[e] += __shfl_down_sync(0xffffffffu, acc[e], off);
  }
  if (lane==0){
    float it = 1.0f / fabsf(temp[0]);
    float p[8]; float m = -1e30f;
    #pragma unroll
    for (int e=0;e<8;e++){ p[e] = (acc[e]+gb[e])*it; m = fmaxf(m, p[e]); }
    float s = 0.f;
    #pragma unroll
    for (int e=0;e<8;e++){ p[e] = expf(p[e]-m); s += p[e]; }
    float inv = 1.f/s;
    #pragma unroll
    for (int e=0;e<8;e++){ p[e] *= inv; atomicAdd(&g_probSum[e], p[e]); }
    // stable top-2 (strict > keeps lower index on ties, matches jax top_k)
    int e0 = 0;
    #pragma unroll
    for (int e=1;e<8;e++) if (p[e] > p[e0]) e0 = e;
    int e1 = (e0==0) ? 1 : 0;
    #pragma unroll
    for (int e=0;e<8;e++) if (e!=e0 && p[e] > p[e1]) e1 = e;
    float rs = 1.f/(p[e0]+p[e1]);
    int s0 = atomicAdd(&g_count[e0], 1);
    g_tok[e0*NTOK+s0] = gwarp; g_wgt[e0*NTOK+s0] = p[e0]*rs; g_pos[e0*NTOK+s0] = gwarp*2;
    int s1 = atomicAdd(&g_count[e1], 1);
    g_tok[e1*NTOK+s1] = gwarp; g_wgt[e1*NTOK+s1] = p[e1]*rs; g_pos[e1*NTOK+s1] = gwarp*2+1;
  }
}

// ---------------- capacity filter (exact jax top-k drop; ~never triggers) ----------------
__global__ void capacity_kernel(){
  int e = blockIdx.x;
  int cnt = g_count[e];
  if (cnt <= CAPACITY) return;
  for (int i = threadIdx.x; i < cnt; i += blockDim.x){
    float wi = g_wgt[e*NTOK+i]; int pi = g_pos[e*NTOK+i];
    int rank = 0;
    for (int j=0;j<cnt;j++){
      float wj = g_wgt[e*NTOK+j];
      if (wj > wi || (wj == wi && g_pos[e*NTOK+j] < pi)) rank++;
    }
    g_drop[e*NTOK+i] = (rank >= CAPACITY) ? 1 : 0;
  }
  __syncthreads();
  for (int i = threadIdx.x; i < cnt; i += blockDim.x)
    if (g_drop[e*NTOK+i]) g_wgt[e*NTOK+i] = 0.f;
}

// ---------------- aux loss ----------------
__global__ void aux_kernel(float* __restrict__ out, int out_size){
  if (threadIdx.x != 0) return;
  float imp[NEXP]; float sum = 0.f;
  for (int e=0;e<NEXP;e++){ imp[e] = g_probSum[e]; sum += imp[e]; }
  float mean = sum / NEXP;
  float var = 0.f;
  for (int e=0;e<NEXP;e++){ float d = imp[e]-mean; var += d*d; }
  var /= (NEXP-1);
  float cv = sqrtf(var) / (mean + 1e-10f);
  float bal = 0.f;
  for (int e=0;e<NEXP;e++)
    bal += (g_probSum[e]/(float)NTOK) * ((float)g_count[e]/(float)NTOK);
  bal *= (float)NEXP;
  if (out_size > NTOK*ODIM) out[(size_t)NTOK*ODIM] = bal + 0.01f*cv;
}

// ---------------- tf32 MMA GEMM ----------------
__device__ __forceinline__ uint32_t f2tf32(float f){
  uint32_t u; asm("cvt.rna.tf32.f32 %0, %1;" : "=r"(u) : "f"(f)); return u;
}
__device__ __forceinline__ void cp16(void* dst, const void* src){
  uint32_t d = (uint32_t)__cvta_generic_to_shared(dst);
  asm volatile("cp.async.cg.shared.global [%0], [%1], 16;" :: "r"(d), "l"(src));
}

#define AS_STRIDE 36
#define BS_STRIDE 136
#define AS_ELEMS (128*AS_STRIDE)
#define BS_ELEMS (32*BS_STRIDE)
#define SMEM_BYTES ((2*AS_ELEMS + 2*BS_ELEMS)*4 + 128*8)

template<int MODE>
__device__ __forceinline__ void load_AB(int stage, int k0, int tid, int e, int row0,
    const float* __restrict__ X, const float* __restrict__ Wb,
    const int* __restrict__ stok, float* As, float* Bs)
{
  float* Ad = As + stage*AS_ELEMS;
  float* Bd = Bs + stage*BS_ELEMS;
  #pragma unroll
  for (int i=0;i<4;i++){
    int s = tid + i*256;
    int r = s >> 3, c4 = (s & 7) << 2;
    const float* src;
    if (MODE==1) src = X + (size_t)stok[r]*DDIM + k0 + c4;
    else         src = g_hbuf + ((size_t)e*ROWS_MAX + row0 + r)*HDIM + k0 + c4;
    cp16(Ad + r*AS_STRIDE + c4, src);
  }
  #pragma unroll
  for (int i=0;i<4;i++){
    int s = tid + i*256;
    int r = s >> 5, c4 = (s & 31) << 2;
    cp16(Bd + r*BS_STRIDE + c4, Wb + (size_t)(k0 + r)*2048 + c4);
  }
}

template<int MODE>
__global__ void __launch_bounds__(256,1) moe_gemm(
    const float* __restrict__ X,      // MODE1: x; MODE2: unused (uses g_hbuf)
    const float* __restrict__ W,      // [E,2048,2048]
    const float* __restrict__ bias,   // [E,2048]
    float* __restrict__ out)          // MODE2 only
{
  int e  = blockIdx.y >> 5;
  int rb = blockIdx.y & 31;
  int cnt = g_count[e]; if (cnt > ROWS_MAX) cnt = ROWS_MAX;
  int row0 = rb * 128;
  if (row0 >= cnt) return;
  int n0 = blockIdx.x * 128;
  int rows = cnt - row0; if (rows > 128) rows = 128;

  extern __shared__ float smem[];
  float* As  = smem;
  float* Bs  = smem + 2*AS_ELEMS;
  int*   stok = (int*)(smem + 2*AS_ELEMS + 2*BS_ELEMS);
  float* swt  = (float*)(stok + 128);

  int tid = threadIdx.x;
  if (tid < 128){
    int t = 0; float w = 0.f;
    if (tid < rows){ t = g_tok[e*NTOK+row0+tid]; w = g_wgt[e*NTOK+row0+tid]; }
    stok[tid] = t; swt[tid] = w;
  }
  __syncthreads();

  const float* Wb = W + (size_t)e*2048*2048 + n0;

  float c[4][4][4];
  #pragma unroll
  for (int a=0;a<4;a++)
    #pragma unroll
    for (int b=0;b<4;b++)
      #pragma unroll
      for (int q=0;q<4;q++) c[a][b][q] = 0.f;

  int warp = tid>>5, lane = tid&31;
  int wm = warp & 1, wn = warp >> 1;
  int lr = lane>>2, lc = lane&3;

  load_AB<MODE>(0, 0, tid, e, row0, X, Wb, stok, As, Bs);
  asm volatile("cp.async.commit_group;" ::: "memory");

  const int NK = 2048/32;
  for (int kt=0; kt<NK; kt++){
    if (kt+1 < NK) load_AB<MODE>((kt+1)&1, (kt+1)*32, tid, e, row0, X, Wb, stok, As, Bs);
    asm volatile("cp.async.commit_group;" ::: "memory");
    asm volatile("cp.async.wait_group 1;" ::: "memory");
    __syncthreads();
    const float* A = As + (kt&1)*AS_ELEMS;
    const float* B = Bs + (kt&1)*BS_ELEMS;
    #pragma unroll
    for (int ks=0; ks<4; ks++){
      uint32_t ua[4][4], ub[4][2];
      #pragma unroll
      for (int mf=0; mf<4; mf++){
        const float* ap = A + (wm*64 + mf*16 + lr)*AS_STRIDE + ks*8 + lc;
        ua[mf][0] = f2tf32(ap[0]);
        ua[mf][1] = f2tf32(ap[8*AS_STRIDE]);
        ua[mf][2] = f2tf32(ap[4]);
        ua[mf][3] = f2tf32(ap[8*AS_STRIDE+4]);
      }
      #pragma unroll
      for (int nf=0; nf<4; nf++){
        const float* bp = B + (ks*8 + lc)*BS_STRIDE + wn*32 + nf*8 + lr;
        ub[nf][0] = f2tf32(bp[0]);
        ub[nf][1] = f2tf32(bp[4*BS_STRIDE]);
      }
      #pragma unroll
      for (int mf=0;mf<4;mf++)
        #pragma unroll
        for (int nf=0;nf<4;nf++)
          asm volatile("mma.sync.aligned.m16n8k8.row.col.f32.tf32.tf32.f32 "
            "{%0,%1,%2,%3}, {%4,%5,%6,%7}, {%8,%9}, {%0,%1,%2,%3};"
            : "+f"(c[mf][nf][0]), "+f"(c[mf][nf][1]), "+f"(c[mf][nf][2]), "+f"(c[mf][nf][3])
            : "r"(ua[mf][0]),"r"(ua[mf][1]),"r"(ua[mf][2]),"r"(ua[mf][3]),
              "r"(ub[nf][0]),"r"(ub[nf][1]));
    }
    __syncthreads();
  }

  // epilogue
  #pragma unroll
  for (int mf=0; mf<4; mf++){
    #pragma unroll
    for (int nf=0; nf<4; nf++){
      int col = n0 + wn*32 + nf*8 + lc*2;
      #pragma unroll
      for (int h=0; h<2; h++){
        int r = wm*64 + mf*16 + lr + h*8;
        if (r < rows){
          float v0 = c[mf][nf][2*h], v1 = c[mf][nf][2*h+1];
          if (MODE==1){
            v0 = fmaxf(v0 + bias[e*2048 + col],   0.f);
            v1 = fmaxf(v1 + bias[e*2048 + col+1], 0.f);
            float2* d = reinterpret_cast<float2*>(
                g_hbuf + ((size_t)e*ROWS_MAX + row0 + r)*HDIM + col);
            *d = make_float2(v0, v1);
          } else {
            float w = swt[r];
            v0 = (v0 + bias[e*2048 + col])   * w;
            v1 = (v1 + bias[e*2048 + col+1]) * w;
            float* d = out + (size_t)stok[r]*ODIM + col;
            atomicAdd(d,   v0);
            atomicAdd(d+1, v1);
          }
        }
      }
    }
  }
}

// ---------------- launch ----------------
extern "C" void kernel_launch(void* const* d_in, const int* in_sizes, int n_in,
                              void* d_out, int out_size){
  const float* x  = (const float*)d_in[0];
  const float* gw = (const float*)d_in[1];
  const float* gb = (const float*)d_in[2];
  const float* tp = (const float*)d_in[3];
  const float* w1 = (const float*)d_in[4];
  const float* b1 = (const float*)d_in[5];
  const float* w2 = (const float*)d_in[6];
  const float* b2 = (const float*)d_in[7];
  float* out = (float*)d_out;

  cudaFuncSetAttribute(moe_gemm<1>, cudaFuncAttributeMaxDynamicSharedMemorySize, SMEM_BYTES);
  cudaFuncSetAttribute(moe_gemm<2>, cudaFuncAttributeMaxDynamicSharedMemorySize, SMEM_BYTES);

  init_kernel<<<2048, 256>>>(x, out);
  router_kernel<<<NTOK/8, 256>>>(x, gw, gb, tp);
  capacity_kernel<<<NEXP, 256>>>();
  aux_kernel<<<1, 32>>>(out, out_size);

  dim3 grid(2048/128, NEXP*RB_PER_E);
  moe_gemm<1><<<grid, 256, SMEM_BYTES>>>(x,       w1, b1, nullptr);
  moe_gemm<2><<<grid, 256, SMEM_BYTES>>>(nullptr, w2, b2, out);
}

// round 4
// speedup vs baseline: 1.1606x; 1.1606x over previous
#include <cuda_runtime.h>
#include <cuda_fp16.h>
#include <cstdint>

#define NTOK   8192
#define EDIM   2048
#define NEXP   8
#define CAPACITY 2560
#define ROWS_MAX 4096
#define KC     64
#define NKC    (EDIM/KC)     // 32 K-chunks

// ---------------- device scratch (no allocs allowed) ----------------
__device__ int    g_count[NEXP];
__device__ float  g_probSum[NEXP];
__device__ int    g_tok[NEXP*NTOK];
__device__ float  g_wgt[NEXP*NTOK];
__device__ int    g_pos[NEXP*NTOK];
__device__ int    g_code[NTOK*2];
__device__ unsigned char g_drop[NEXP*NTOK];
__device__ __half g_w16[(size_t)2*NEXP*EDIM*EDIM];        // 134 MB (w1|w2 fp16)
__device__ __half g_x16[(size_t)NTOK*EDIM];               // 33 MB
__device__ __half g_h16[(size_t)NEXP*ROWS_MAX*EDIM];      // 134 MB
__device__ float  g_ybuf[(size_t)NEXP*ROWS_MAX*EDIM];     // 268 MB

// ---------------- helpers ----------------
__device__ __forceinline__ uint32_t smem_u32(const void* p){
  uint32_t a; asm("{ .reg .u64 t; cvta.to.shared.u64 t, %1; cvt.u32.u64 %0, t; }" : "=r"(a) : "l"(p));
  return a;
}
__device__ __forceinline__ void cpa16(uint32_t dst, const void* src){
  asm volatile("cp.async.cg.shared.global [%0], [%1], 16;" :: "r"(dst), "l"(src));
}

// ---------------- init ----------------
__global__ void init_kernel(){
  if (threadIdx.x < NEXP){ g_count[threadIdx.x] = 0; g_probSum[threadIdx.x] = 0.f; }
}

// ---------------- fp32 -> fp16 conversion of weights and x ----------------
__global__ void convert_kernel(const float* __restrict__ w1, const float* __restrict__ w2,
                               const float* __restrict__ x){
  const size_t NW = (size_t)NEXP*EDIM*EDIM;      // 33.5M per layer
  const size_t NX = (size_t)NTOK*EDIM;           // 16.7M
  size_t i = (size_t)blockIdx.x*blockDim.x + threadIdx.x;
  size_t stride = (size_t)gridDim.x*blockDim.x;
  uint2* o1 = reinterpret_cast<uint2*>(g_w16);
  uint2* o2 = reinterpret_cast<uint2*>(g_w16 + NW);
  uint2* ox = reinterpret_cast<uint2*>(g_x16);
  const float4* s1 = reinterpret_cast<const float4*>(w1);
  const float4* s2 = reinterpret_cast<const float4*>(w2);
  const float4* sx = reinterpret_cast<const float4*>(x);
  for (size_t j=i; j<NW/4; j+=stride){
    float4 v = s1[j];
    __half2 a = __floats2half2_rn(v.x,v.y), b = __floats2half2_rn(v.z,v.w);
    o1[j] = make_uint2(*(uint32_t*)&a, *(uint32_t*)&b);
    v = s2[j];
    a = __floats2half2_rn(v.x,v.y); b = __floats2half2_rn(v.z,v.w);
    o2[j] = make_uint2(*(uint32_t*)&a, *(uint32_t*)&b);
  }
  for (size_t j=i; j<NX/4; j+=stride){
    float4 v = sx[j];
    __half2 a = __floats2half2_rn(v.x,v.y), b = __floats2half2_rn(v.z,v.w);
    ox[j] = make_uint2(*(uint32_t*)&a, *(uint32_t*)&b);
  }
}

// ---------------- router: warp per token ----------------
__global__ void router_kernel(const float* __restrict__ x, const float* __restrict__ gw,
                              const float* __restrict__ gb, const float* __restrict__ temp){
  int t = (int)((blockIdx.x*blockDim.x + threadIdx.x) >> 5);
  int lane = threadIdx.x & 31;
  if (t >= NTOK) return;
  const float* xr = x + (size_t)t * EDIM;
  float acc[8] = {0,0,0,0,0,0,0,0};
  for (int d = lane; d < EDIM; d += 32){
    float xv = xr[d];
    const float4* g4 = reinterpret_cast<const float4*>(gw + (size_t)d*NEXP);
    float4 ga = g4[0], gbv = g4[1];
    acc[0] += xv*ga.x;  acc[1] += xv*ga.y;  acc[2] += xv*ga.z;  acc[3] += xv*ga.w;
    acc[4] += xv*gbv.x; acc[5] += xv*gbv.y; acc[6] += xv*gbv.z; acc[7] += xv*gbv.w;
  }
  #pragma unroll
  for (int off=16; off; off>>=1)
    #pragma unroll
    for (int e=0;e<8;e++) acc[e] += __shfl_down_sync(0xffffffffu, acc[e], off);
  if (lane==0){
    float it = 1.0f / fabsf(temp[0]);
    float p[8]; float m = -1e30f;
    #pragma unroll
    for (int e=0;e<8;e++){ p[e] = (acc[e]+gb[e])*it; m = fmaxf(m, p[e]); }
    float s = 0.f;
    #pragma unroll
    for (int e=0;e<8;e++){ p[e] = expf(p[e]-m); s += p[e]; }
    float inv = 1.f/s;
    #pragma unroll
    for (int e=0;e<8;e++){ p[e] *= inv; atomicAdd(&g_probSum[e], p[e]); }
    int e0 = 0;
    #pragma unroll
    for (int e=1;e<8;e++) if (p[e] > p[e0]) e0 = e;
    int e1 = (e0==0) ? 1 : 0;
    #pragma unroll
    for (int e=0;e<8;e++) if (e!=e0 && p[e] > p[e1]) e1 = e;
    float rs = 1.f/(p[e0]+p[e1]);
    int s0 = atomicAdd(&g_count[e0], 1);
    g_tok[e0*NTOK+s0] = t; g_wgt[e0*NTOK+s0] = p[e0]*rs; g_pos[e0*NTOK+s0] = t*2;
    g_code[t*2+0] = e0*NTOK + s0;
    int s1 = atomicAdd(&g_count[e1], 1);
    g_tok[e1*NTOK+s1] = t; g_wgt[e1*NTOK+s1] = p[e1]*rs; g_pos[e1*NTOK+s1] = t*2+1;
    g_code[t*2+1] = e1*NTOK + s1;
  }
}

// ---------------- capacity filter (exact jax semantics; ~never triggers) ----------------
__global__ void capacity_kernel(){
  int e = blockIdx.x;
  int cnt = g_count[e];
  if (cnt <= CAPACITY) return;
  for (int i = threadIdx.x; i < cnt; i += blockDim.x){
    float wi = g_wgt[e*NTOK+i]; int pi = g_pos[e*NTOK+i];
    int rank = 0;
    for (int j=0;j<cnt;j++){
      float wj = g_wgt[e*NTOK+j];
      if (wj > wi || (wj == wi && g_pos[e*NTOK+j] < pi)) rank++;
    }
    g_drop[e*NTOK+i] = (rank >= CAPACITY) ? 1 : 0;
  }
  __syncthreads();
  for (int i = threadIdx.x; i < cnt; i += blockDim.x)
    if (g_drop[e*NTOK+i]) g_wgt[e*NTOK+i] = 0.f;
}

// ---------------- aux loss ----------------
__global__ void aux_kernel(float* __restrict__ out, int out_size){
  if (threadIdx.x != 0) return;
  float sum = 0.f;
  for (int e=0;e<NEXP;e++) sum += g_probSum[e];
  float mean = sum / NEXP;
  float var = 0.f;
  for (int e=0;e<NEXP;e++){ float d = g_probSum[e]-mean; var += d*d; }
  var /= (NEXP-1);
  float cv = sqrtf(var) / (mean + 1e-10f);
  float bal = 0.f;
  for (int e=0;e<NEXP;e++)
    bal += (g_probSum[e]/(float)NTOK) * ((float)g_count[e]/(float)NTOK);
  bal *= (float)NEXP;
  if (out_size > NTOK*EDIM) out[(size_t)NTOK*EDIM] = bal + 0.01f*cv;
}

// ---------------- fp16 mma.sync GEMM, 128x256x64-chunk, 4-stage cp.async ----------------
// smem layout per stage: A 16KB (128x64 fp16, ldmatrix-native 8x8 blocks),
//                        B 32KB (64x256 fp16, ldmatrix-native)
#define A_ST 16384
#define B_ST 32768
#define STAGE_BYTES (A_ST + B_ST)
#define NSTAGE 4
#define META_OFF (NSTAGE*STAGE_BYTES)       // 196608
#define SMEM_TOTAL (META_OFF + 768)

template<int MODE>
__device__ __forceinline__ void load_stage(
    int kt, int slot, int tid, uint32_t sbase,
    const __half* __restrict__ Xg, const __half* __restrict__ Wb,
    const int* __restrict__ stok)
{
  int k0 = kt*KC;
  uint32_t ab = sbase + slot*STAGE_BYTES;
  uint32_t bb = ab + A_ST;
  // A: 128 rows x 64 cols fp16 -> 1024 x 16B (each 16B = one 8-wide k-octet row of an 8x8 block)
  #pragma unroll
  for (int i=0;i<4;i++){
    int idx = tid + i*256;
    int r = idx >> 3, ko = idx & 7;           // ko: k-octet 0..7, k = ko*8
    size_t grow = (MODE==1) ? (size_t)stok[r] : (size_t)r;
    const __half* src = Xg + grow*EDIM + k0 + ko*8;
    uint32_t dst = ab + (uint32_t)(((r>>4)*4 + (ko>>1))*512
                 + ((r&8)?128:0) + ((ko&1)?256:0) + (r&7)*16);
    cpa16(dst, src);
  }
  // B: 64 k-rows x 256 n cols fp16 -> 2048 x 16B
  #pragma unroll
  for (int i=0;i<8;i++){
    int idx = tid + i*256;
    int kr = idx >> 5, no = idx & 31;         // n = no*8
    const __half* src = Wb + (size_t)(k0+kr)*EDIM + no*8;
    uint32_t dst = bb + (uint32_t)(((kr>>4)*16 + (no>>1))*512
                 + ((kr&8)?128:0) + ((no&1)?256:0) + (kr&7)*16);
    cpa16(dst, src);
  }
  asm volatile("cp.async.commit_group;" ::: "memory");
}

template<int MODE>
__global__ void __launch_bounds__(256,1) moe_gemm(
    const float* __restrict__ bias)
{
  int e  = blockIdx.y >> 5;
  int rb = blockIdx.y & 31;
  int cnt = g_count[e]; if (cnt > ROWS_MAX) cnt = ROWS_MAX;
  int row0 = rb * 128;
  if (row0 >= cnt) return;
  int rows = cnt - row0; if (rows > 128) rows = 128;
  int n0 = blockIdx.x * 256;

  extern __shared__ char smem[];
  uint32_t sbase = smem_u32(smem);
  int tid = threadIdx.x, warp = tid>>5, lane = tid&31;
  int* stok = (int*)(smem + META_OFF);

  if (tid < 128){
    int tkn = 0;
    if (MODE==1 && tid < rows) tkn = g_tok[e*NTOK + row0 + tid];
    stok[tid] = tkn;
  }
  __syncthreads();

  const __half* Xg = (MODE==1) ? g_x16 : (g_h16 + ((size_t)e*ROWS_MAX + row0)*EDIM);
  const __half* Wb = g_w16 + ((size_t)((MODE-1)*NEXP + e))*EDIM*EDIM + n0;

  float c[4][8][4];
  #pragma unroll
  for (int a=0;a<4;a++)
    #pragma unroll
    for (int b=0;b<8;b++)
      #pragma unroll
      for (int q=0;q<4;q++) c[a][b][q] = 0.f;

  int wm = warp & 1, wn = warp >> 1;   // 2 x 4 warp grid, each 64(M) x 64(N)

  #pragma unroll
  for (int p=0;p<3;p++) load_stage<MODE>(p, p, tid, sbase, Xg, Wb, stok);

  for (int kt=0; kt<NKC; kt++){
    int slot = kt & 3;
    if (kt+3 < NKC){
      load_stage<MODE>(kt+3, (kt+3)&3, tid, sbase, Xg, Wb, stok);
      asm volatile("cp.async.wait_group 3;" ::: "memory");
    } else if (kt+2 < NKC) asm volatile("cp.async.wait_group 2;" ::: "memory");
    else if   (kt+1 < NKC) asm volatile("cp.async.wait_group 1;" ::: "memory");
    else                   asm volatile("cp.async.wait_group 0;" ::: "memory");
    __syncthreads();

    uint32_t ab = sbase + slot*STAGE_BYTES;
    uint32_t bb = ab + A_ST;
    #pragma unroll
    for (int ks=0; ks<4; ks++){
      uint32_t a[4][4];
      #pragma unroll
      for (int mf=0; mf<4; mf++){
        uint32_t addr = ab + (uint32_t)((((wm*4+mf)*4)+ks)*512) + lane*16;
        asm volatile("ldmatrix.sync.aligned.m8n8.x4.shared.b16 {%0,%1,%2,%3}, [%4];"
          : "=r"(a[mf][0]),"=r"(a[mf][1]),"=r"(a[mf][2]),"=r"(a[mf][3]) : "r"(addr));
      }
      uint32_t b[8][2];
      #pragma unroll
      for (int p=0; p<4; p++){
        uint32_t addr = bb + (uint32_t)((ks*16 + wn*4 + p)*512) + lane*16;
        asm volatile("ldmatrix.sync.aligned.m8n8.x4.trans.shared.b16 {%0,%1,%2,%3}, [%4];"
          : "=r"(b[2*p][0]),"=r"(b[2*p][1]),"=r"(b[2*p+1][0]),"=r"(b[2*p+1][1]) : "r"(addr));
      }
      #pragma unroll
      for (int mf=0; mf<4; mf++)
        #pragma unroll
        for (int nf=0; nf<8; nf++)
          asm volatile("mma.sync.aligned.m16n8k16.row.col.f32.f16.f16.f32 "
            "{%0,%1,%2,%3}, {%4,%5,%6,%7}, {%8,%9}, {%0,%1,%2,%3};"
            : "+f"(c[mf][nf][0]), "+f"(c[mf][nf][1]), "+f"(c[mf][nf][2]), "+f"(c[mf][nf][3])
            : "r"(a[mf][0]),"r"(a[mf][1]),"r"(a[mf][2]),"r"(a[mf][3]),
              "r"(b[nf][0]),"r"(b[nf][1]));
    }
    __syncthreads();
  }

  // ---------------- epilogue (registers -> gmem) ----------------
  int lr = lane>>2, lc = lane&3;
  const float* brow = bias + e*EDIM + n0 + wn*64;
  if (MODE==1){
    __half* hb = g_h16 + ((size_t)e*ROWS_MAX + row0)*EDIM + n0 + wn*64;
    #pragma unroll
    for (int nf=0; nf<8; nf++){
      int col = nf*8 + lc*2;
      float bv0 = brow[col], bv1 = brow[col+1];
      #pragma unroll
      for (int mf=0; mf<4; mf++){
        int r_ = wm*64 + mf*16 + lr;
        if (r_ < rows){
          __half2 h = __floats2half2_rn(fmaxf(c[mf][nf][0]+bv0,0.f), fmaxf(c[mf][nf][1]+bv1,0.f));
          *reinterpret_cast<__half2*>(hb + (size_t)r_*EDIM + col) = h;
        }
        if (r_+8 < rows){
          __half2 h = __floats2half2_rn(fmaxf(c[mf][nf][2]+bv0,0.f), fmaxf(c[mf][nf][3]+bv1,0.f));
          *reinterpret_cast<__half2*>(hb + (size_t)(r_+8)*EDIM + col) = h;
        }
      }
    }
  } else {
    float* yb = g_ybuf + ((size_t)e*ROWS_MAX + row0)*EDIM + n0 + wn*64;
    #pragma unroll
    for (int nf=0; nf<8; nf++){
      int col = nf*8 + lc*2;
      float bv0 = brow[col], bv1 = brow[col+1];
      #pragma unroll
      for (int mf=0; mf<4; mf++){
        int r_ = wm*64 + mf*16 + lr;
        if (r_ < rows)
          *reinterpret_cast<float2*>(yb + (size_t)r_*EDIM + col)
              = make_float2(c[mf][nf][0]+bv0, c[mf][nf][1]+bv1);
        if (r_+8 < rows)
          *reinterpret_cast<float2*>(yb + (size_t)(r_+8)*EDIM + col)
              = make_float2(c[mf][nf][2]+bv0, c[mf][nf][3]+bv1);
      }
    }
  }
}

// ---------------- combine: out = x + w0*y0 + w1*y1 ----------------
__global__ void combine_kernel(const float* __restrict__ x, float* __restrict__ out){
  int t = blockIdx.x;
  int c1 = g_code[2*t], c2 = g_code[2*t+1];
  int s1 = c1 & (NTOK-1), s2 = c2 & (NTOK-1);
  float w1v = (s1 < ROWS_MAX) ? g_wgt[c1] : 0.f;
  float w2v = (s2 < ROWS_MAX) ? g_wgt[c2] : 0.f;
  size_t y1o = (s1 < ROWS_MAX) ? ((size_t)(c1>>13)*ROWS_MAX + s1)*EDIM : 0;
  size_t y2o = (s2 < ROWS_MAX) ? ((size_t)(c2>>13)*ROWS_MAX + s2)*EDIM : 0;
  const float4* xr = reinterpret_cast<const float4*>(x + (size_t)t*EDIM);
  const float4* y1 = reinterpret_cast<const float4*>(g_ybuf + y1o);
  const float4* y2 = reinterpret_cast<const float4*>(g_ybuf + y2o);
  float4* o = reinterpret_cast<float4*>(out + (size_t)t*EDIM);
  for (int j = threadIdx.x; j < EDIM/4; j += blockDim.x){
    float4 a = xr[j], b = y1[j], c = y2[j];
    float4 rr;
    rr.x = a.x + w1v*b.x + w2v*c.x;
    rr.y = a.y + w1v*b.y + w2v*c.y;
    rr.z = a.z + w1v*b.z + w2v*c.z;
    rr.w = a.w + w1v*b.w + w2v*c.w;
    o[j] = rr;
  }
}

// ---------------- launch ----------------
extern "C" void kernel_launch(void* const* d_in, const int* in_sizes, int n_in,
                              void* d_out, int out_size){
  const float* x  = (const float*)d_in[0];
  const float* gw = (const float*)d_in[1];
  const float* gb = (const float*)d_in[2];
  const float* tp = (const float*)d_in[3];
  const float* w1 = (const float*)d_in[4];
  const float* b1 = (const float*)d_in[5];
  const float* w2 = (const float*)d_in[6];
  const float* b2 = (const float*)d_in[7];
  float* out = (float*)d_out;

  cudaFuncSetAttribute(moe_gemm<1>, cudaFuncAttributeMaxDynamicSharedMemorySize, SMEM_TOTAL);
  cudaFuncSetAttribute(moe_gemm<2>, cudaFuncAttributeMaxDynamicSharedMemorySize, SMEM_TOTAL);

  init_kernel<<<1, 64>>>();
  convert_kernel<<<1024, 256>>>(w1, w2, x);
  router_kernel<<<NTOK/8, 256>>>(x, gw, gb, tp);
  capacity_kernel<<<NEXP, 256>>>();
  aux_kernel<<<1, 32>>>(out, out_size);

  dim3 grid(EDIM/256, NEXP*32);
  moe_gemm<1><<<grid, 256, SMEM_TOTAL>>>(b1);
  moe_gemm<2><<<grid, 256, SMEM_TOTAL>>>(b2);
  combine_kernel<<<NTOK, 256>>>(x, out);
}

// round 5
// speedup vs baseline: 1.1784x; 1.0153x over previous
#include <cuda_runtime.h>
#include <cuda_fp16.h>
#include <cstdint>

#define NTOK   8192
#define EDIM   2048
#define NEXP   8
#define CAPACITY 2560
#define ROWS_MAX 4096
#define KC     64
#define NKC    (EDIM/KC)     // 32 K-chunks

// ---------------- device scratch (no allocs allowed) ----------------
__device__ int    g_count[NEXP];
__device__ float  g_probSum[NEXP];
__device__ int    g_tok[NEXP*NTOK];
__device__ float  g_wgt[NEXP*NTOK];
__device__ int    g_pos[NEXP*NTOK];
__device__ int    g_code[NTOK*2];
__device__ unsigned char g_drop[NEXP*NTOK];
__device__ __half g_w16[(size_t)2*NEXP*EDIM*EDIM];        // 134 MB (w1|w2 fp16)
__device__ __half g_x16[(size_t)NTOK*EDIM];               // 33 MB
__device__ __half g_h16[(size_t)NEXP*ROWS_MAX*EDIM];      // 134 MB
__device__ float  g_ybuf[(size_t)NEXP*ROWS_MAX*EDIM];     // 268 MB

// ---------------- helpers ----------------
__device__ __forceinline__ uint32_t smem_u32(const void* p){
  uint32_t a; asm("{ .reg .u64 t; cvta.to.shared.u64 t, %1; cvt.u32.u64 %0, t; }" : "=r"(a) : "l"(p));
  return a;
}
__device__ __forceinline__ void cpa16(uint32_t dst, const void* src){
  asm volatile("cp.async.cg.shared.global [%0], [%1], 16;" :: "r"(dst), "l"(src));
}

// ---------------- init ----------------
__global__ void init_kernel(){
  if (threadIdx.x < NEXP){ g_count[threadIdx.x] = 0; g_probSum[threadIdx.x] = 0.f; }
}

// ---------------- fp32 -> fp16 conversion of weights and x ----------------
__global__ void convert_kernel(const float* __restrict__ w1, const float* __restrict__ w2,
                               const float* __restrict__ x){
  const size_t NW = (size_t)NEXP*EDIM*EDIM;
  const size_t NX = (size_t)NTOK*EDIM;
  size_t i = (size_t)blockIdx.x*blockDim.x + threadIdx.x;
  size_t stride = (size_t)gridDim.x*blockDim.x;
  uint2* o1 = reinterpret_cast<uint2*>(g_w16);
  uint2* o2 = reinterpret_cast<uint2*>(g_w16 + NW);
  uint2* ox = reinterpret_cast<uint2*>(g_x16);
  const float4* s1 = reinterpret_cast<const float4*>(w1);
  const float4* s2 = reinterpret_cast<const float4*>(w2);
  const float4* sx = reinterpret_cast<const float4*>(x);
  for (size_t j=i; j<NW/4; j+=stride){
    float4 v = s1[j];
    __half2 a = __floats2half2_rn(v.x,v.y), b = __floats2half2_rn(v.z,v.w);
    o1[j] = make_uint2(*(uint32_t*)&a, *(uint32_t*)&b);
    v = s2[j];
    a = __floats2half2_rn(v.x,v.y); b = __floats2half2_rn(v.z,v.w);
    o2[j] = make_uint2(*(uint32_t*)&a, *(uint32_t*)&b);
  }
  for (size_t j=i; j<NX/4; j+=stride){
    float4 v = sx[j];
    __half2 a = __floats2half2_rn(v.x,v.y), b = __floats2half2_rn(v.z,v.w);
    ox[j] = make_uint2(*(uint32_t*)&a, *(uint32_t*)&b);
  }
}

// ---------------- router: warp per token ----------------
__global__ void router_kernel(const float* __restrict__ x, const float* __restrict__ gw,
                              const float* __restrict__ gb, const float* __restrict__ temp){
  int t = (int)((blockIdx.x*blockDim.x + threadIdx.x) >> 5);
  int lane = threadIdx.x & 31;
  if (t >= NTOK) return;
  const float* xr = x + (size_t)t * EDIM;
  float acc[8] = {0,0,0,0,0,0,0,0};
  for (int d = lane; d < EDIM; d += 32){
    float xv = xr[d];
    const float4* g4 = reinterpret_cast<const float4*>(gw + (size_t)d*NEXP);
    float4 ga = g4[0], gbv = g4[1];
    acc[0] += xv*ga.x;  acc[1] += xv*ga.y;  acc[2] += xv*ga.z;  acc[3] += xv*ga.w;
    acc[4] += xv*gbv.x; acc[5] += xv*gbv.y; acc[6] += xv*gbv.z; acc[7] += xv*gbv.w;
  }
  #pragma unroll
  for (int off=16; off; off>>=1)
    #pragma unroll
    for (int e=0;e<8;e++) acc[e] += __shfl_down_sync(0xffffffffu, acc[e], off);
  if (lane==0){
    float it = 1.0f / fabsf(temp[0]);
    float p[8]; float m = -1e30f;
    #pragma unroll
    for (int e=0;e<8;e++){ p[e] = (acc[e]+gb[e])*it; m = fmaxf(m, p[e]); }
    float s = 0.f;
    #pragma unroll
    for (int e=0;e<8;e++){ p[e] = expf(p[e]-m); s += p[e]; }
    float inv = 1.f/s;
    #pragma unroll
    for (int e=0;e<8;e++){ p[e] *= inv; atomicAdd(&g_probSum[e], p[e]); }
    int e0 = 0;
    #pragma unroll
    for (int e=1;e<8;e++) if (p[e] > p[e0]) e0 = e;
    int e1 = (e0==0) ? 1 : 0;
    #pragma unroll
    for (int e=0;e<8;e++) if (e!=e0 && p[e] > p[e1]) e1 = e;
    float rs = 1.f/(p[e0]+p[e1]);
    int s0 = atomicAdd(&g_count[e0], 1);
    g_tok[e0*NTOK+s0] = t; g_wgt[e0*NTOK+s0] = p[e0]*rs; g_pos[e0*NTOK+s0] = t*2;
    g_code[t*2+0] = e0*NTOK + s0;
    int s1 = atomicAdd(&g_count[e1], 1);
    g_tok[e1*NTOK+s1] = t; g_wgt[e1*NTOK+s1] = p[e1]*rs; g_pos[e1*NTOK+s1] = t*2+1;
    g_code[t*2+1] = e1*NTOK + s1;
  }
}

// ---------------- capacity filter (exact jax semantics; ~never triggers) ----------------
__global__ void capacity_kernel(){
  int e = blockIdx.x;
  int cnt = g_count[e];
  if (cnt <= CAPACITY) return;
  for (int i = threadIdx.x; i < cnt; i += blockDim.x){
    float wi = g_wgt[e*NTOK+i]; int pi = g_pos[e*NTOK+i];
    int rank = 0;
    for (int j=0;j<cnt;j++){
      float wj = g_wgt[e*NTOK+j];
      if (wj > wi || (wj == wi && g_pos[e*NTOK+j] < pi)) rank++;
    }
    g_drop[e*NTOK+i] = (rank >= CAPACITY) ? 1 : 0;
  }
  __syncthreads();
  for (int i = threadIdx.x; i < cnt; i += blockDim.x)
    if (g_drop[e*NTOK+i]) g_wgt[e*NTOK+i] = 0.f;
}

// ---------------- aux loss ----------------
__global__ void aux_kernel(float* __restrict__ out, int out_size){
  if (threadIdx.x != 0) return;
  float sum = 0.f;
  for (int e=0;e<NEXP;e++) sum += g_probSum[e];
  float mean = sum / NEXP;
  float var = 0.f;
  for (int e=0;e<NEXP;e++){ float d = g_probSum[e]-mean; var += d*d; }
  var /= (NEXP-1);
  float cv = sqrtf(var) / (mean + 1e-10f);
  float bal = 0.f;
  for (int e=0;e<NEXP;e++)
    bal += (g_probSum[e]/(float)NTOK) * ((float)g_count[e]/(float)NTOK);
  bal *= (float)NEXP;
  if (out_size > NTOK*EDIM) out[(size_t)NTOK*EDIM] = bal + 0.01f*cv;
}

// ---------------- fp16 mma.sync GEMM, 128x128x64-chunk, 3-stage, 2 CTA/SM ----------------
// per stage: A 16KB (128x64 fp16) + B 16KB (64x128 fp16), ldmatrix-native 8x8 blocks
#define A_ST 16384
#define B_ST 16384
#define STAGE_BYTES (A_ST + B_ST)
#define NSTAGE 3
#define META_OFF (NSTAGE*STAGE_BYTES)       // 98304
#define SMEM_TOTAL (META_OFF + 768)

template<int MODE>
__device__ __forceinline__ void load_stage(
    int kt, int slot, int tid, uint32_t sbase,
    const __half* __restrict__ Xg, const __half* __restrict__ Wb,
    const int* __restrict__ stok)
{
  int k0 = kt*KC;
  uint32_t ab = sbase + slot*STAGE_BYTES;
  uint32_t bb = ab + A_ST;
  // A: 128 rows x 64 k fp16 -> 1024 x 16B
  #pragma unroll
  for (int i=0;i<4;i++){
    int idx = tid + i*256;
    int r = idx >> 3, ko = idx & 7;           // k = ko*8
    size_t grow = (MODE==1) ? (size_t)stok[r] : (size_t)r;
    const __half* src = Xg + grow*EDIM + k0 + ko*8;
    uint32_t dst = ab + (uint32_t)(((r>>4)*4 + (ko>>1))*512
                 + ((r&8)?128:0) + ((ko&1)?256:0) + (r&7)*16);
    cpa16(dst, src);
  }
  // B: 64 k-rows x 128 n fp16 -> 1024 x 16B
  #pragma unroll
  for (int i=0;i<4;i++){
    int idx = tid + i*256;
    int kr = idx >> 4, no = idx & 15;         // n = no*8
    const __half* src = Wb + (size_t)(k0+kr)*EDIM + no*8;
    uint32_t dst = bb + (uint32_t)(((kr>>4)*8 + (no>>1))*512
                 + ((kr&8)?128:0) + ((no&1)?256:0) + (kr&7)*16);
    cpa16(dst, src);
  }
  asm volatile("cp.async.commit_group;" ::: "memory");
}

template<int MODE>
__global__ void __launch_bounds__(256,2) moe_gemm(
    const float* __restrict__ bias)
{
  int e  = blockIdx.y >> 5;
  int rb = blockIdx.y & 31;
  int cnt = g_count[e]; if (cnt > ROWS_MAX) cnt = ROWS_MAX;
  int row0 = rb * 128;
  if (row0 >= cnt) return;
  int rows = cnt - row0; if (rows > 128) rows = 128;
  int n0 = blockIdx.x * 128;

  extern __shared__ char smem[];
  uint32_t sbase = smem_u32(smem);
  int tid = threadIdx.x, warp = tid>>5, lane = tid&31;
  int* stok = (int*)(smem + META_OFF);

  if (tid < 128){
    int tkn = 0;
    if (MODE==1 && tid < rows) tkn = g_tok[e*NTOK + row0 + tid];
    stok[tid] = tkn;
  }
  __syncthreads();

  const __half* Xg = (MODE==1) ? g_x16 : (g_h16 + ((size_t)e*ROWS_MAX + row0)*EDIM);
  const __half* Wb = g_w16 + ((size_t)((MODE-1)*NEXP + e))*EDIM*EDIM + n0;

  float c[4][4][4];
  #pragma unroll
  for (int a=0;a<4;a++)
    #pragma unroll
    for (int b=0;b<4;b++)
      #pragma unroll
      for (int q=0;q<4;q++) c[a][b][q] = 0.f;

  int wm = warp & 1, wn = warp >> 1;   // 2 x 4 warp grid: 64(M) x 32(N) each

  load_stage<MODE>(0, 0, tid, sbase, Xg, Wb, stok);
  load_stage<MODE>(1, 1, tid, sbase, Xg, Wb, stok);

  for (int kt=0; kt<NKC; kt++){
    int slot = kt % 3;
    if (kt+1 < NKC) asm volatile("cp.async.wait_group 1;" ::: "memory");
    else            asm volatile("cp.async.wait_group 0;" ::: "memory");
    __syncthreads();
    if (kt+2 < NKC) load_stage<MODE>(kt+2, (kt+2)%3, tid, sbase, Xg, Wb, stok);

    uint32_t ab = sbase + slot*STAGE_BYTES;
    uint32_t bb = ab + A_ST;
    #pragma unroll
    for (int ks=0; ks<4; ks++){
      uint32_t a[4][4];
      #pragma unroll
      for (int mf=0; mf<4; mf++){
        uint32_t addr = ab + (uint32_t)(((wm*4+mf)*4 + ks)*512) + lane*16;
        asm volatile("ldmatrix.sync.aligned.m8n8.x4.shared.b16 {%0,%1,%2,%3}, [%4];"
          : "=r"(a[mf][0]),"=r"(a[mf][1]),"=r"(a[mf][2]),"=r"(a[mf][3]) : "r"(addr));
      }
      uint32_t b[4][2];
      #pragma unroll
      for (int p=0; p<2; p++){
        uint32_t addr = bb + (uint32_t)((ks*8 + wn*2 + p)*512) + lane*16;
        asm volatile("ldmatrix.sync.aligned.m8n8.x4.trans.shared.b16 {%0,%1,%2,%3}, [%4];"
          : "=r"(b[2*p][0]),"=r"(b[2*p][1]),"=r"(b[2*p+1][0]),"=r"(b[2*p+1][1]) : "r"(addr));
      }
      #pragma unroll
      for (int mf=0; mf<4; mf++)
        #pragma unroll
        for (int nf=0; nf<4; nf++)
          asm volatile("mma.sync.aligned.m16n8k16.row.col.f32.f16.f16.f32 "
            "{%0,%1,%2,%3}, {%4,%5,%6,%7}, {%8,%9}, {%0,%1,%2,%3};"
            : "+f"(c[mf][nf][0]), "+f"(c[mf][nf][1]), "+f"(c[mf][nf][2]), "+f"(c[mf][nf][3])
            : "r"(a[mf][0]),"r"(a[mf][1]),"r"(a[mf][2]),"r"(a[mf][3]),
              "r"(b[nf][0]),"r"(b[nf][1]));
    }
  }

  // ---------------- epilogue (registers -> gmem) ----------------
  int lr = lane>>2, lc = lane&3;
  const float* brow = bias + e*EDIM + n0 + wn*32;
  if (MODE==1){
    __half* hb = g_h16 + ((size_t)e*ROWS_MAX + row0)*EDIM + n0 + wn*32;
    #pragma unroll
    for (int nf=0; nf<4; nf++){
      int col = nf*8 + lc*2;
      float bv0 = brow[col], bv1 = brow[col+1];
      #pragma unroll
      for (int mf=0; mf<4; mf++){
        int r_ = wm*64 + mf*16 + lr;
        if (r_ < rows){
          __half2 h = __floats2half2_rn(fmaxf(c[mf][nf][0]+bv0,0.f), fmaxf(c[mf][nf][1]+bv1,0.f));
          *reinterpret_cast<__half2*>(hb + (size_t)r_*EDIM + col) = h;
        }
        if (r_+8 < rows){
          __half2 h = __floats2half2_rn(fmaxf(c[mf][nf][2]+bv0,0.f), fmaxf(c[mf][nf][3]+bv1,0.f));
          *reinterpret_cast<__half2*>(hb + (size_t)(r_+8)*EDIM + col) = h;
        }
      }
    }
  } else {
    float* yb = g_ybuf + ((size_t)e*ROWS_MAX + row0)*EDIM + n0 + wn*32;
    #pragma unroll
    for (int nf=0; nf<4; nf++){
      int col = nf*8 + lc*2;
      float bv0 = brow[col], bv1 = brow[col+1];
      #pragma unroll
      for (int mf=0; mf<4; mf++){
        int r_ = wm*64 + mf*16 + lr;
        if (r_ < rows)
          *reinterpret_cast<float2*>(yb + (size_t)r_*EDIM + col)
              = make_float2(c[mf][nf][0]+bv0, c[mf][nf][1]+bv1);
        if (r_+8 < rows)
          *reinterpret_cast<float2*>(yb + (size_t)(r_+8)*EDIM + col)
              = make_float2(c[mf][nf][2]+bv0, c[mf][nf][3]+bv1);
      }
    }
  }
}

// ---------------- combine: out = x + w0*y0 + w1*y1 ----------------
__global__ void combine_kernel(const float* __restrict__ x, float* __restrict__ out){
  int t = blockIdx.x;
  int c1 = g_code[2*t], c2 = g_code[2*t+1];
  int s1 = c1 & (NTOK-1), s2 = c2 & (NTOK-1);
  float w1v = (s1 < ROWS_MAX) ? g_wgt[c1] : 0.f;
  float w2v = (s2 < ROWS_MAX) ? g_wgt[c2] : 0.f;
  size_t y1o = (s1 < ROWS_MAX) ? ((size_t)(c1>>13)*ROWS_MAX + s1)*EDIM : 0;
  size_t y2o = (s2 < ROWS_MAX) ? ((size_t)(c2>>13)*ROWS_MAX + s2)*EDIM : 0;
  const float4* xr = reinterpret_cast<const float4*>(x + (size_t)t*EDIM);
  const float4* y1 = reinterpret_cast<const float4*>(g_ybuf + y1o);
  const float4* y2 = reinterpret_cast<const float4*>(g_ybuf + y2o);
  float4* o = reinterpret_cast<float4*>(out + (size_t)t*EDIM);
  for (int j = threadIdx.x; j < EDIM/4; j += blockDim.x){
    float4 a = xr[j], b = y1[j], c = y2[j];
    float4 rr;
    rr.x = a.x + w1v*b.x + w2v*c.x;
    rr.y = a.y + w1v*b.y + w2v*c.y;
    rr.z = a.z + w1v*b.z + w2v*c.z;
    rr.w = a.w + w1v*b.w + w2v*c.w;
    o[j] = rr;
  }
}

// ---------------- launch ----------------
extern "C" void kernel_launch(void* const* d_in, const int* in_sizes, int n_in,
                              void* d_out, int out_size){
  const float* x  = (const float*)d_in[0];
  const float* gw = (const float*)d_in[1];
  const float* gb = (const float*)d_in[2];
  const float* tp = (const float*)d_in[3];
  const float* w1 = (const float*)d_in[4];
  const float* b1 = (const float*)d_in[5];
  const float* w2 = (const float*)d_in[6];
  const float* b2 = (const float*)d_in[7];
  float* out = (float*)d_out;

  cudaFuncSetAttribute(moe_gemm<1>, cudaFuncAttributeMaxDynamicSharedMemorySize, SMEM_TOTAL);
  cudaFuncSetAttribute(moe_gemm<2>, cudaFuncAttributeMaxDynamicSharedMemorySize, SMEM_TOTAL);

  init_kernel<<<1, 64>>>();
  convert_kernel<<<1024, 256>>>(w1, w2, x);
  router_kernel<<<NTOK/8, 256>>>(x, gw, gb, tp);
  capacity_kernel<<<NEXP, 256>>>();
  aux_kernel<<<1, 32>>>(out, out_size);

  dim3 grid(EDIM/128, NEXP*32);
  moe_gemm<1><<<grid, 256, SMEM_TOTAL>>>(b1);
  moe_gemm<2><<<grid, 256, SMEM_TOTAL>>>(b2);
  combine_kernel<<<NTOK, 256>>>(x, out);
}

// round 6
// speedup vs baseline: 1.1859x; 1.0064x over previous
#include <cuda_runtime.h>
#include <cuda_fp16.h>
#include <cstdint>

#define NTOK   8192
#define EDIM   2048
#define NEXP   8
#define CAPACITY 2560
#define ROWS_MAX 4096
#define KC     64
#define NKC    (EDIM/KC)     // 32 K-chunks

// ---------------- device scratch (no allocs allowed) ----------------
__device__ int    g_count[NEXP];
__device__ float  g_probSum[NEXP];
__device__ int    g_tok[NEXP*NTOK];
__device__ float  g_wgt[NEXP*NTOK];
__device__ int    g_pos[NEXP*NTOK];
__device__ int    g_code[NTOK*2];
__device__ unsigned char g_drop[NEXP*NTOK];
__device__ __half g_w16[(size_t)2*NEXP*EDIM*EDIM];        // 134 MB (w1|w2 fp16)
__device__ __half g_x16[(size_t)NTOK*EDIM];               // 33 MB
__device__ __half g_h16[(size_t)NEXP*ROWS_MAX*EDIM];      // 134 MB
__device__ float  g_ybuf[(size_t)NEXP*ROWS_MAX*EDIM];     // 268 MB

// ---------------- helpers ----------------
__device__ __forceinline__ uint32_t smem_u32(const void* p){
  uint32_t a; asm("{ .reg .u64 t; cvta.to.shared.u64 t, %1; cvt.u32.u64 %0, t; }" : "=r"(a) : "l"(p));
  return a;
}
__device__ __forceinline__ void cpa16(uint32_t dst, const void* src){
  asm volatile("cp.async.cg.shared.global [%0], [%1], 16;" :: "r"(dst), "l"(src));
}

// ---------------- fp32 -> fp16 conversion of weights and x (+ counter init) ----------------
__global__ void convert_kernel(const float* __restrict__ w1, const float* __restrict__ w2,
                               const float* __restrict__ x){
  if (blockIdx.x == 0 && threadIdx.x < NEXP){
    g_count[threadIdx.x] = 0; g_probSum[threadIdx.x] = 0.f;
  }
  const size_t NW = (size_t)NEXP*EDIM*EDIM;
  const size_t NX = (size_t)NTOK*EDIM;
  size_t i = (size_t)blockIdx.x*blockDim.x + threadIdx.x;
  size_t stride = (size_t)gridDim.x*blockDim.x;
  uint2* o1 = reinterpret_cast<uint2*>(g_w16);
  uint2* o2 = reinterpret_cast<uint2*>(g_w16 + NW);
  uint2* ox = reinterpret_cast<uint2*>(g_x16);
  const float4* s1 = reinterpret_cast<const float4*>(w1);
  const float4* s2 = reinterpret_cast<const float4*>(w2);
  const float4* sx = reinterpret_cast<const float4*>(x);
  for (size_t j=i; j<NW/4; j+=stride){
    float4 v = s1[j];
    __half2 a = __floats2half2_rn(v.x,v.y), b = __floats2half2_rn(v.z,v.w);
    o1[j] = make_uint2(*(uint32_t*)&a, *(uint32_t*)&b);
    v = s2[j];
    a = __floats2half2_rn(v.x,v.y); b = __floats2half2_rn(v.z,v.w);
    o2[j] = make_uint2(*(uint32_t*)&a, *(uint32_t*)&b);
  }
  for (size_t j=i; j<NX/4; j+=stride){
    float4 v = sx[j];
    __half2 a = __floats2half2_rn(v.x,v.y), b = __floats2half2_rn(v.z,v.w);
    ox[j] = make_uint2(*(uint32_t*)&a, *(uint32_t*)&b);
  }
}

// ---------------- router: warp per token ----------------
__global__ void router_kernel(const float* __restrict__ x, const float* __restrict__ gw,
                              const float* __restrict__ gb, const float* __restrict__ temp){
  int t = (int)((blockIdx.x*blockDim.x + threadIdx.x) >> 5);
  int lane = threadIdx.x & 31;
  if (t >= NTOK) return;
  const float* xr = x + (size_t)t * EDIM;
  float acc[8] = {0,0,0,0,0,0,0,0};
  for (int d = lane; d < EDIM; d += 32){
    float xv = xr[d];
    const float4* g4 = reinterpret_cast<const float4*>(gw + (size_t)d*NEXP);
    float4 ga = g4[0], gbv = g4[1];
    acc[0] += xv*ga.x;  acc[1] += xv*ga.y;  acc[2] += xv*ga.z;  acc[3] += xv*ga.w;
    acc[4] += xv*gbv.x; acc[5] += xv*gbv.y; acc[6] += xv*gbv.z; acc[7] += xv*gbv.w;
  }
  #pragma unroll
  for (int off=16; off; off>>=1)
    #pragma unroll
    for (int e=0;e<8;e++) acc[e] += __shfl_down_sync(0xffffffffu, acc[e], off);
  if (lane==0){
    float it = 1.0f / fabsf(temp[0]);
    float p[8]; float m = -1e30f;
    #pragma unroll
    for (int e=0;e<8;e++){ p[e] = (acc[e]+gb[e])*it; m = fmaxf(m, p[e]); }
    float s = 0.f;
    #pragma unroll
    for (int e=0;e<8;e++){ p[e] = expf(p[e]-m); s += p[e]; }
    float inv = 1.f/s;
    #pragma unroll
    for (int e=0;e<8;e++){ p[e] *= inv; atomicAdd(&g_probSum[e], p[e]); }
    int e0 = 0;
    #pragma unroll
    for (int e=1;e<8;e++) if (p[e] > p[e0]) e0 = e;
    int e1 = (e0==0) ? 1 : 0;
    #pragma unroll
    for (int e=0;e<8;e++) if (e!=e0 && p[e] > p[e1]) e1 = e;
    float rs = 1.f/(p[e0]+p[e1]);
    int s0 = atomicAdd(&g_count[e0], 1);
    g_tok[e0*NTOK+s0] = t; g_wgt[e0*NTOK+s0] = p[e0]*rs; g_pos[e0*NTOK+s0] = t*2;
    g_code[t*2+0] = e0*NTOK + s0;
    int s1 = atomicAdd(&g_count[e1], 1);
    g_tok[e1*NTOK+s1] = t; g_wgt[e1*NTOK+s1] = p[e1]*rs; g_pos[e1*NTOK+s1] = t*2+1;
    g_code[t*2+1] = e1*NTOK + s1;
  }
}

// ---------------- capacity filter (exact jax semantics; ~never triggers) ----------------
__global__ void capacity_kernel(){
  int e = blockIdx.x;
  int cnt = g_count[e];
  if (cnt <= CAPACITY) return;
  for (int i = threadIdx.x; i < cnt; i += blockDim.x){
    float wi = g_wgt[e*NTOK+i]; int pi = g_pos[e*NTOK+i];
    int rank = 0;
    for (int j=0;j<cnt;j++){
      float wj = g_wgt[e*NTOK+j];
      if (wj > wi || (wj == wi && g_pos[e*NTOK+j] < pi)) rank++;
    }
    g_drop[e*NTOK+i] = (rank >= CAPACITY) ? 1 : 0;
  }
  __syncthreads();
  for (int i = threadIdx.x; i < cnt; i += blockDim.x)
    if (g_drop[e*NTOK+i]) g_wgt[e*NTOK+i] = 0.f;
}

// ---------------- aux loss ----------------
__global__ void aux_kernel(float* __restrict__ out, int out_size){
  if (threadIdx.x != 0) return;
  float sum = 0.f;
  for (int e=0;e<NEXP;e++) sum += g_probSum[e];
  float mean = sum / NEXP;
  float var = 0.f;
  for (int e=0;e<NEXP;e++){ float d = g_probSum[e]-mean; var += d*d; }
  var /= (NEXP-1);
  float cv = sqrtf(var) / (mean + 1e-10f);
  float bal = 0.f;
  for (int e=0;e<NEXP;e++)
    bal += (g_probSum[e]/(float)NTOK) * ((float)g_count[e]/(float)NTOK);
  bal *= (float)NEXP;
  if (out_size > NTOK*EDIM) out[(size_t)NTOK*EDIM] = bal + 0.01f*cv;
}

// ---------------- fp16 mma.sync GEMM, 128x128x64-chunk, 3-stage, 2 CTA/SM ----------------
#define A_ST 16384
#define B_ST 16384
#define STAGE_BYTES (A_ST + B_ST)
#define NSTAGE 3
#define META_OFF (NSTAGE*STAGE_BYTES)       // 98304
#define SMEM_TOTAL (META_OFF + 768)

template<int MODE>
__device__ __forceinline__ void load_stage(
    int kt, int slot, int tid, uint32_t sbase,
    const __half* __restrict__ Xg, const __half* __restrict__ Wb,
    const int* __restrict__ stok)
{
  int k0 = kt*KC;
  uint32_t ab = sbase + slot*STAGE_BYTES;
  uint32_t bb = ab + A_ST;
  #pragma unroll
  for (int i=0;i<4;i++){
    int idx = tid + i*256;
    int r = idx >> 3, ko = idx & 7;
    size_t grow = (MODE==1) ? (size_t)stok[r] : (size_t)r;
    const __half* src = Xg + grow*EDIM + k0 + ko*8;
    uint32_t dst = ab + (uint32_t)(((r>>4)*4 + (ko>>1))*512
                 + ((r&8)?128:0) + ((ko&1)?256:0) + (r&7)*16);
    cpa16(dst, src);
  }
  #pragma unroll
  for (int i=0;i<4;i++){
    int idx = tid + i*256;
    int kr = idx >> 4, no = idx & 15;
    const __half* src = Wb + (size_t)(k0+kr)*EDIM + no*8;
    uint32_t dst = bb + (uint32_t)(((kr>>4)*8 + (no>>1))*512
                 + ((kr&8)?128:0) + ((no&1)?256:0) + (kr&7)*16);
    cpa16(dst, src);
  }
  asm volatile("cp.async.commit_group;" ::: "memory");
}

__device__ __forceinline__ void ldsm_frags(
    uint32_t ab, uint32_t bb, int wm, int wn, int lane, int ks,
    uint32_t a[4][4], uint32_t b[4][2])
{
  #pragma unroll
  for (int mf=0; mf<4; mf++){
    uint32_t addr = ab + (uint32_t)(((wm*4+mf)*4 + ks)*512) + lane*16;
    asm volatile("ldmatrix.sync.aligned.m8n8.x4.shared.b16 {%0,%1,%2,%3}, [%4];"
      : "=r"(a[mf][0]),"=r"(a[mf][1]),"=r"(a[mf][2]),"=r"(a[mf][3]) : "r"(addr));
  }
  #pragma unroll
  for (int p=0; p<2; p++){
    uint32_t addr = bb + (uint32_t)((ks*8 + wn*2 + p)*512) + lane*16;
    asm volatile("ldmatrix.sync.aligned.m8n8.x4.trans.shared.b16 {%0,%1,%2,%3}, [%4];"
      : "=r"(b[2*p][0]),"=r"(b[2*p][1]),"=r"(b[2*p+1][0]),"=r"(b[2*p+1][1]) : "r"(addr));
  }
}

template<int MODE>
__global__ void __launch_bounds__(256,2) moe_gemm(
    const float* __restrict__ bias)
{
  int e  = blockIdx.y >> 5;
  int rb = blockIdx.y & 31;
  int cnt = g_count[e]; if (cnt > ROWS_MAX) cnt = ROWS_MAX;
  int row0 = rb * 128;
  if (row0 >= cnt) return;
  int rows = cnt - row0; if (rows > 128) rows = 128;
  int n0 = blockIdx.x * 128;

  extern __shared__ char smem[];
  uint32_t sbase = smem_u32(smem);
  int tid = threadIdx.x, warp = tid>>5, lane = tid&31;
  int* stok = (int*)(smem + META_OFF);

  if (tid < 128){
    int tkn = 0;
    if (MODE==1 && tid < rows) tkn = g_tok[e*NTOK + row0 + tid];
    stok[tid] = tkn;
  }
  __syncthreads();

  const __half* Xg = (MODE==1) ? g_x16 : (g_h16 + ((size_t)e*ROWS_MAX + row0)*EDIM);
  const __half* Wb = g_w16 + ((size_t)((MODE-1)*NEXP + e))*EDIM*EDIM + n0;

  float c[4][4][4];
  #pragma unroll
  for (int a=0;a<4;a++)
    #pragma unroll
    for (int b=0;b<4;b++)
      #pragma unroll
      for (int q=0;q<4;q++) c[a][b][q] = 0.f;

  int wm = warp & 1, wn = warp >> 1;   // 2 x 4 warp grid: 64(M) x 32(N) each

  load_stage<MODE>(0, 0, tid, sbase, Xg, Wb, stok);
  load_stage<MODE>(1, 1, tid, sbase, Xg, Wb, stok);

  uint32_t af[2][4][4], bf[2][4][2];

  for (int kt=0; kt<NKC; kt++){
    int slot = kt % 3;
    if (kt+1 < NKC) asm volatile("cp.async.wait_group 1;" ::: "memory");
    else            asm volatile("cp.async.wait_group 0;" ::: "memory");
    __syncthreads();
    if (kt+2 < NKC) load_stage<MODE>(kt+2, (kt+2)%3, tid, sbase, Xg, Wb, stok);

    uint32_t ab = sbase + slot*STAGE_BYTES;
    uint32_t bb = ab + A_ST;

    ldsm_frags(ab, bb, wm, wn, lane, 0, af[0], bf[0]);
    #pragma unroll
    for (int ks=0; ks<4; ks++){
      if (ks < 3) ldsm_frags(ab, bb, wm, wn, lane, ks+1, af[(ks+1)&1], bf[(ks+1)&1]);
      uint32_t (*a)[4] = af[ks&1];
      uint32_t (*b)[2] = bf[ks&1];
      #pragma unroll
      for (int mf=0; mf<4; mf++)
        #pragma unroll
        for (int nf=0; nf<4; nf++)
          asm volatile("mma.sync.aligned.m16n8k16.row.col.f32.f16.f16.f32 "
            "{%0,%1,%2,%3}, {%4,%5,%6,%7}, {%8,%9}, {%0,%1,%2,%3};"
            : "+f"(c[mf][nf][0]), "+f"(c[mf][nf][1]), "+f"(c[mf][nf][2]), "+f"(c[mf][nf][3])
            : "r"(a[mf][0]),"r"(a[mf][1]),"r"(a[mf][2]),"r"(a[mf][3]),
              "r"(b[nf][0]),"r"(b[nf][1]));
    }
  }

  // ---------------- epilogue (registers -> gmem) ----------------
  int lr = lane>>2, lc = lane&3;
  const float* brow = bias + e*EDIM + n0 + wn*32;
  if (MODE==1){
    __half* hb = g_h16 + ((size_t)e*ROWS_MAX + row0)*EDIM + n0 + wn*32;
    #pragma unroll
    for (int nf=0; nf<4; nf++){
      int col = nf*8 + lc*2;
      float bv0 = brow[col], bv1 = brow[col+1];
      #pragma unroll
      for (int mf=0; mf<4; mf++){
        int r_ = wm*64 + mf*16 + lr;
        if (r_ < rows){
          __half2 h = __floats2half2_rn(fmaxf(c[mf][nf][0]+bv0,0.f), fmaxf(c[mf][nf][1]+bv1,0.f));
          *reinterpret_cast<__half2*>(hb + (size_t)r_*EDIM + col) = h;
        }
        if (r_+8 < rows){
          __half2 h = __floats2half2_rn(fmaxf(c[mf][nf][2]+bv0,0.f), fmaxf(c[mf][nf][3]+bv1,0.f));
          *reinterpret_cast<__half2*>(hb + (size_t)(r_+8)*EDIM + col) = h;
        }
      }
    }
  } else {
    float* yb = g_ybuf + ((size_t)e*ROWS_MAX + row0)*EDIM + n0 + wn*32;
    #pragma unroll
    for (int nf=0; nf<4; nf++){
      int col = nf*8 + lc*2;
      float bv0 = brow[col], bv1 = brow[col+1];
      #pragma unroll
      for (int mf=0; mf<4; mf++){
        int r_ = wm*64 + mf*16 + lr;
        if (r_ < rows)
          *reinterpret_cast<float2*>(yb + (size_t)r_*EDIM + col)
              = make_float2(c[mf][nf][0]+bv0, c[mf][nf][1]+bv1);
        if (r_+8 < rows)
          *reinterpret_cast<float2*>(yb + (size_t)(r_+8)*EDIM + col)
              = make_float2(c[mf][nf][2]+bv0, c[mf][nf][3]+bv1);
      }
    }
  }
}

// ---------------- combine: out = x + w0*y0 + w1*y1 ----------------
__global__ void combine_kernel(const float* __restrict__ x, float* __restrict__ out){
  int t = blockIdx.x;
  int c1 = g_code[2*t], c2 = g_code[2*t+1];
  int s1 = c1 & (NTOK-1), s2 = c2 & (NTOK-1);
  float w1v = (s1 < ROWS_MAX) ? g_wgt[c1] : 0.f;
  float w2v = (s2 < ROWS_MAX) ? g_wgt[c2] : 0.f;
  size_t y1o = (s1 < ROWS_MAX) ? ((size_t)(c1>>13)*ROWS_MAX + s1)*EDIM : 0;
  size_t y2o = (s2 < ROWS_MAX) ? ((size_t)(c2>>13)*ROWS_MAX + s2)*EDIM : 0;
  const float4* xr = reinterpret_cast<const float4*>(x + (size_t)t*EDIM);
  const float4* y1 = reinterpret_cast<const float4*>(g_ybuf + y1o);
  const float4* y2 = reinterpret_cast<const float4*>(g_ybuf + y2o);
  float4* o = reinterpret_cast<float4*>(out + (size_t)t*EDIM);
  for (int j = threadIdx.x; j < EDIM/4; j += blockDim.x){
    float4 a = xr[j], b = y1[j], c = y2[j];
    float4 rr;
    rr.x = a.x + w1v*b.x + w2v*c.x;
    rr.y = a.y + w1v*b.y + w2v*c.y;
    rr.z = a.z + w1v*b.z + w2v*c.z;
    rr.w = a.w + w1v*b.w + w2v*c.w;
    o[j] = rr;
  }
}

// ---------------- launch ----------------
extern "C" void kernel_launch(void* const* d_in, const int* in_sizes, int n_in,
                              void* d_out, int out_size){
  const float* x  = (const float*)d_in[0];
  const float* gw = (const float*)d_in[1];
  const float* gb = (const float*)d_in[2];
  const float* tp = (const float*)d_in[3];
  const float* w1 = (const float*)d_in[4];
  const float* b1 = (const float*)d_in[5];
  const float* w2 = (const float*)d_in[6];
  const float* b2 = (const float*)d_in[7];
  float* out = (float*)d_out;

  cudaFuncSetAttribute(moe_gemm<1>, cudaFuncAttributeMaxDynamicSharedMemorySize, SMEM_TOTAL);
  cudaFuncSetAttribute(moe_gemm<2>, cudaFuncAttributeMaxDynamicSharedMemorySize, SMEM_TOTAL);

  // Launch order chosen so moe_gemm<1> is our 4th launch (ncu -s 5 lands there
  // given the harness's 2 internal launches).
  convert_kernel<<<1024, 256>>>(w1, w2, x);           // idx 0 (also inits counters)
  router_kernel<<<NTOK/8, 256>>>(x, gw, gb, tp);      // idx 1
  capacity_kernel<<<NEXP, 256>>>();                   // idx 2
  dim3 grid(EDIM/128, NEXP*32);
  moe_gemm<1><<<grid, 256, SMEM_TOTAL>>>(b1);         // idx 3  <-- profiled
  moe_gemm<2><<<grid, 256, SMEM_TOTAL>>>(b2);         // idx 4
  aux_kernel<<<1, 32>>>(out, out_size);               // idx 5
  combine_kernel<<<NTOK, 256>>>(x, out);              // idx 6
}

// round 7
// speedup vs baseline: 1.2672x; 1.0686x over previous
#include <cuda_runtime.h>
#include <cuda_fp16.h>
#include <cstdint>

#define NTOK   8192
#define EDIM   2048
#define NEXP   8
#define CAPACITY 2560
#define ROWS_MAX 4096
#define KC     64
#define NKC    (EDIM/KC)     // 32 K-chunks

// ---------------- device scratch (no allocs allowed) ----------------
__device__ int    g_count[NEXP];
__device__ float  g_probSum[NEXP];
__device__ int    g_tok[NEXP*NTOK];
__device__ float  g_wgt[NEXP*NTOK];
__device__ int    g_pos[NEXP*NTOK];
__device__ int    g_code[NTOK*2];
__device__ unsigned char g_drop[NEXP*NTOK];
__device__ __half g_w16[(size_t)2*NEXP*EDIM*EDIM];        // 134 MB (w1|w2 fp16)
__device__ __half g_x16[(size_t)NTOK*EDIM];               // 33 MB
__device__ __half g_h16[(size_t)NEXP*ROWS_MAX*EDIM];      // 134 MB
__device__ float  g_ybuf[(size_t)NEXP*ROWS_MAX*EDIM];     // 268 MB

// ---------------- helpers ----------------
__device__ __forceinline__ uint32_t smem_u32(const void* p){
  uint32_t a; asm("{ .reg .u64 t; cvta.to.shared.u64 t, %1; cvt.u32.u64 %0, t; }" : "=r"(a) : "l"(p));
  return a;
}
__device__ __forceinline__ void cpa16(uint32_t dst, const void* src){
  asm volatile("cp.async.cg.shared.global [%0], [%1], 16;" :: "r"(dst), "l"(src));
}

// ---------------- fp32 -> fp16 conversion of weights and x (+ counter init) ----------------
__global__ void convert_kernel(const float* __restrict__ w1, const float* __restrict__ w2,
                               const float* __restrict__ x){
  if (blockIdx.x == 0 && threadIdx.x < NEXP){
    g_count[threadIdx.x] = 0; g_probSum[threadIdx.x] = 0.f;
  }
  const size_t NW = (size_t)NEXP*EDIM*EDIM;
  const size_t NX = (size_t)NTOK*EDIM;
  size_t i = (size_t)blockIdx.x*blockDim.x + threadIdx.x;
  size_t stride = (size_t)gridDim.x*blockDim.x;
  uint2* o1 = reinterpret_cast<uint2*>(g_w16);
  uint2* o2 = reinterpret_cast<uint2*>(g_w16 + NW);
  uint2* ox = reinterpret_cast<uint2*>(g_x16);
  const float4* s1 = reinterpret_cast<const float4*>(w1);
  const float4* s2 = reinterpret_cast<const float4*>(w2);
  const float4* sx = reinterpret_cast<const float4*>(x);
  for (size_t j=i; j<NW/4; j+=stride){
    float4 v = s1[j];
    __half2 a = __floats2half2_rn(v.x,v.y), b = __floats2half2_rn(v.z,v.w);
    o1[j] = make_uint2(*(uint32_t*)&a, *(uint32_t*)&b);
    v = s2[j];
    a = __floats2half2_rn(v.x,v.y); b = __floats2half2_rn(v.z,v.w);
    o2[j] = make_uint2(*(uint32_t*)&a, *(uint32_t*)&b);
  }
  for (size_t j=i; j<NX/4; j+=stride){
    float4 v = sx[j];
    __half2 a = __floats2half2_rn(v.x,v.y), b = __floats2half2_rn(v.z,v.w);
    ox[j] = make_uint2(*(uint32_t*)&a, *(uint32_t*)&b);
  }
}

// ---------------- router: warp per token ----------------
__global__ void router_kernel(const float* __restrict__ x, const float* __restrict__ gw,
                              const float* __restrict__ gb, const float* __restrict__ temp){
  int t = (int)((blockIdx.x*blockDim.x + threadIdx.x) >> 5);
  int lane = threadIdx.x & 31;
  if (t >= NTOK) return;
  const float* xr = x + (size_t)t * EDIM;
  float acc[8] = {0,0,0,0,0,0,0,0};
  for (int d = lane; d < EDIM; d += 32){
    float xv = xr[d];
    const float4* g4 = reinterpret_cast<const float4*>(gw + (size_t)d*NEXP);
    float4 ga = g4[0], gbv = g4[1];
    acc[0] += xv*ga.x;  acc[1] += xv*ga.y;  acc[2] += xv*ga.z;  acc[3] += xv*ga.w;
    acc[4] += xv*gbv.x; acc[5] += xv*gbv.y; acc[6] += xv*gbv.z; acc[7] += xv*gbv.w;
  }
  #pragma unroll
  for (int off=16; off; off>>=1)
    #pragma unroll
    for (int e=0;e<8;e++) acc[e] += __shfl_down_sync(0xffffffffu, acc[e], off);
  if (lane==0){
    float it = 1.0f / fabsf(temp[0]);
    float p[8]; float m = -1e30f;
    #pragma unroll
    for (int e=0;e<8;e++){ p[e] = (acc[e]+gb[e])*it; m = fmaxf(m, p[e]); }
    float s = 0.f;
    #pragma unroll
    for (int e=0;e<8;e++){ p[e] = expf(p[e]-m); s += p[e]; }
    float inv = 1.f/s;
    #pragma unroll
    for (int e=0;e<8;e++){ p[e] *= inv; atomicAdd(&g_probSum[e], p[e]); }
    int e0 = 0;
    #pragma unroll
    for (int e=1;e<8;e++) if (p[e] > p[e0]) e0 = e;
    int e1 = (e0==0) ? 1 : 0;
    #pragma unroll
    for (int e=0;e<8;e++) if (e!=e0 && p[e] > p[e1]) e1 = e;
    float rs = 1.f/(p[e0]+p[e1]);
    int s0 = atomicAdd(&g_count[e0], 1);
    g_tok[e0*NTOK+s0] = t; g_wgt[e0*NTOK+s0] = p[e0]*rs; g_pos[e0*NTOK+s0] = t*2;
    g_code[t*2+0] = e0*NTOK + s0;
    int s1 = atomicAdd(&g_count[e1], 1);
    g_tok[e1*NTOK+s1] = t; g_wgt[e1*NTOK+s1] = p[e1]*rs; g_pos[e1*NTOK+s1] = t*2+1;
    g_code[t*2+1] = e1*NTOK + s1;
  }
}

// ---------------- capacity filter (exact jax semantics; ~never triggers) ----------------
__global__ void capacity_kernel(){
  int e = blockIdx.x;
  int cnt = g_count[e];
  if (cnt <= CAPACITY) return;
  for (int i = threadIdx.x; i < cnt; i += blockDim.x){
    float wi = g_wgt[e*NTOK+i]; int pi = g_pos[e*NTOK+i];
    int rank = 0;
    for (int j=0;j<cnt;j++){
      float wj = g_wgt[e*NTOK+j];
      if (wj > wi || (wj == wi && g_pos[e*NTOK+j] < pi)) rank++;
    }
    g_drop[e*NTOK+i] = (rank >= CAPACITY) ? 1 : 0;
  }
  __syncthreads();
  for (int i = threadIdx.x; i < cnt; i += blockDim.x)
    if (g_drop[e*NTOK+i]) g_wgt[e*NTOK+i] = 0.f;
}

// ---------------- aux loss ----------------
__global__ void aux_kernel(float* __restrict__ out, int out_size){
  if (threadIdx.x != 0) return;
  float sum = 0.f;
  for (int e=0;e<NEXP;e++) sum += g_probSum[e];
  float mean = sum / NEXP;
  float var = 0.f;
  for (int e=0;e<NEXP;e++){ float d = g_probSum[e]-mean; var += d*d; }
  var /= (NEXP-1);
  float cv = sqrtf(var) / (mean + 1e-10f);
  float bal = 0.f;
  for (int e=0;e<NEXP;e++)
    bal += (g_probSum[e]/(float)NTOK) * ((float)g_count[e]/(float)NTOK);
  bal *= (float)NEXP;
  if (out_size > NTOK*EDIM) out[(size_t)NTOK*EDIM] = bal + 0.01f*cv;
}

// ---------------- fp16 mma.sync GEMM, 128x128x64-chunk, 3-stage, 2 CTA/SM ----------------
#define A_ST 16384
#define B_ST 16384
#define STAGE_BYTES (A_ST + B_ST)
#define NSTAGE 3
#define META_OFF (NSTAGE*STAGE_BYTES)       // 98304
#define SMEM_TOTAL (META_OFF + 768)

template<int MODE>
__device__ __forceinline__ void load_A_half(
    int kt, int slot, int tid, uint32_t sbase,
    const __half* __restrict__ Xg, const int* __restrict__ stok)
{
  int k0 = kt*KC;
  uint32_t ab = sbase + slot*STAGE_BYTES;
  #pragma unroll
  for (int i=0;i<4;i++){
    int idx = tid + i*256;
    int r = idx >> 3, ko = idx & 7;
    size_t grow = (MODE==1) ? (size_t)stok[r] : (size_t)r;
    const __half* src = Xg + grow*EDIM + k0 + ko*8;
    uint32_t dst = ab + (uint32_t)(((r>>4)*4 + (ko>>1))*512
                 + ((r&8)?128:0) + ((ko&1)?256:0) + (r&7)*16);
    cpa16(dst, src);
  }
}
__device__ __forceinline__ void load_B_half(
    int kt, int slot, int tid, uint32_t sbase,
    const __half* __restrict__ Wb)
{
  int k0 = kt*KC;
  uint32_t bb = sbase + slot*STAGE_BYTES + A_ST;
  #pragma unroll
  for (int i=0;i<4;i++){
    int idx = tid + i*256;
    int kr = idx >> 4, no = idx & 15;
    const __half* src = Wb + (size_t)(k0+kr)*EDIM + no*8;
    uint32_t dst = bb + (uint32_t)(((kr>>4)*8 + (no>>1))*512
                 + ((kr&8)?128:0) + ((no&1)?256:0) + (kr&7)*16);
    cpa16(dst, src);
  }
}

template<int MODE>
__global__ void __launch_bounds__(256,2) moe_gemm(
    const float* __restrict__ bias)
{
  int e  = blockIdx.y >> 5;
  int rb = blockIdx.y & 31;
  int cnt = g_count[e]; if (cnt > ROWS_MAX) cnt = ROWS_MAX;
  int row0 = rb * 128;
  if (row0 >= cnt) return;
  int rows = cnt - row0; if (rows > 128) rows = 128;
  int n0 = blockIdx.x * 128;

  extern __shared__ char smem[];
  uint32_t sbase = smem_u32(smem);
  int tid = threadIdx.x, warp = tid>>5, lane = tid&31;
  int* stok = (int*)(smem + META_OFF);

  if (tid < 128){
    int tkn = 0;
    if (MODE==1 && tid < rows) tkn = g_tok[e*NTOK + row0 + tid];
    stok[tid] = tkn;
  }
  __syncthreads();

  const __half* Xg = (MODE==1) ? g_x16 : (g_h16 + ((size_t)e*ROWS_MAX + row0)*EDIM);
  const __half* Wb = g_w16 + ((size_t)((MODE-1)*NEXP + e))*EDIM*EDIM + n0;

  float c[4][4][4];
  #pragma unroll
  for (int a=0;a<4;a++)
    #pragma unroll
    for (int b=0;b<4;b++)
      #pragma unroll
      for (int q=0;q<4;q++) c[a][b][q] = 0.f;

  int wm = warp & 1, wn = warp >> 1;   // 2 x 4 warp grid: 64(M) x 32(N) each

  load_A_half<MODE>(0, 0, tid, sbase, Xg, stok);
  load_B_half(0, 0, tid, sbase, Wb);
  asm volatile("cp.async.commit_group;" ::: "memory");
  load_A_half<MODE>(1, 1, tid, sbase, Xg, stok);
  load_B_half(1, 1, tid, sbase, Wb);
  asm volatile("cp.async.commit_group;" ::: "memory");

  for (int kt=0; kt<NKC; kt++){
    int slot = kt % 3;
    if (kt+1 < NKC) asm volatile("cp.async.wait_group 1;" ::: "memory");
    else            asm volatile("cp.async.wait_group 0;" ::: "memory");
    __syncthreads();

    uint32_t ab = sbase + slot*STAGE_BYTES;
    uint32_t bb = ab + A_ST;
    int nslot = (kt+2) % 3;
    bool pref = (kt+2 < NKC);

    #pragma unroll
    for (int ks=0; ks<4; ks++){
      uint32_t a[4][4], b[4][2];
      #pragma unroll
      for (int mf=0; mf<4; mf++){
        uint32_t addr = ab + (uint32_t)(((wm*4+mf)*4 + ks)*512) + lane*16;
        asm volatile("ldmatrix.sync.aligned.m8n8.x4.shared.b16 {%0,%1,%2,%3}, [%4];"
          : "=r"(a[mf][0]),"=r"(a[mf][1]),"=r"(a[mf][2]),"=r"(a[mf][3]) : "r"(addr));
      }
      #pragma unroll
      for (int p=0; p<2; p++){
        uint32_t addr = bb + (uint32_t)((ks*8 + wn*2 + p)*512) + lane*16;
        asm volatile("ldmatrix.sync.aligned.m8n8.x4.trans.shared.b16 {%0,%1,%2,%3}, [%4];"
          : "=r"(b[2*p][0]),"=r"(b[2*p][1]),"=r"(b[2*p+1][0]),"=r"(b[2*p+1][1]) : "r"(addr));
      }
      #pragma unroll
      for (int mf=0; mf<4; mf++)
        #pragma unroll
        for (int nf=0; nf<4; nf++)
          asm volatile("mma.sync.aligned.m16n8k16.row.col.f32.f16.f16.f32 "
            "{%0,%1,%2,%3}, {%4,%5,%6,%7}, {%8,%9}, {%0,%1,%2,%3};"
            : "+f"(c[mf][nf][0]), "+f"(c[mf][nf][1]), "+f"(c[mf][nf][2]), "+f"(c[mf][nf][3])
            : "r"(a[mf][0]),"r"(a[mf][1]),"r"(a[mf][2]),"r"(a[mf][3]),
              "r"(b[nf][0]),"r"(b[nf][1]));

      // interleaved prefetch issue: keep LSU off the chunk-start critical path
      if (ks==0 && pref) load_A_half<MODE>(kt+2, nslot, tid, sbase, Xg, stok);
      if (ks==1 && pref) load_B_half(kt+2, nslot, tid, sbase, Wb);
      if (ks==2 && pref) asm volatile("cp.async.commit_group;" ::: "memory");
    }
  }

  // ---------------- epilogue (registers -> gmem) ----------------
  int lr = lane>>2, lc = lane&3;
  const float* brow = bias + e*EDIM + n0 + wn*32;
  if (MODE==1){
    __half* hb = g_h16 + ((size_t)e*ROWS_MAX + row0)*EDIM + n0 + wn*32;
    #pragma unroll
    for (int nf=0; nf<4; nf++){
      int col = nf*8 + lc*2;
      float bv0 = brow[col], bv1 = brow[col+1];
      #pragma unroll
      for (int mf=0; mf<4; mf++){
        int r_ = wm*64 + mf*16 + lr;
        if (r_ < rows){
          __half2 h = __floats2half2_rn(fmaxf(c[mf][nf][0]+bv0,0.f), fmaxf(c[mf][nf][1]+bv1,0.f));
          *reinterpret_cast<__half2*>(hb + (size_t)r_*EDIM + col) = h;
        }
        if (r_+8 < rows){
          __half2 h = __floats2half2_rn(fmaxf(c[mf][nf][2]+bv0,0.f), fmaxf(c[mf][nf][3]+bv1,0.f));
          *reinterpret_cast<__half2*>(hb + (size_t)(r_+8)*EDIM + col) = h;
        }
      }
    }
  } else {
    float* yb = g_ybuf + ((size_t)e*ROWS_MAX + row0)*EDIM + n0 + wn*32;
    #pragma unroll
    for (int nf=0; nf<4; nf++){
      int col = nf*8 + lc*2;
      float bv0 = brow[col], bv1 = brow[col+1];
      #pragma unroll
      for (int mf=0; mf<4; mf++){
        int r_ = wm*64 + mf*16 + lr;
        if (r_ < rows)
          *reinterpret_cast<float2*>(yb + (size_t)r_*EDIM + col)
              = make_float2(c[mf][nf][0]+bv0, c[mf][nf][1]+bv1);
        if (r_+8 < rows)
          *reinterpret_cast<float2*>(yb + (size_t)(r_+8)*EDIM + col)
              = make_float2(c[mf][nf][2]+bv0, c[mf][nf][3]+bv1);
      }
    }
  }
}

// ---------------- combine: out = x + w0*y0 + w1*y1 ----------------
__global__ void combine_kernel(const float* __restrict__ x, float* __restrict__ out){
  int t = blockIdx.x;
  int c1 = g_code[2*t], c2 = g_code[2*t+1];
  int s1 = c1 & (NTOK-1), s2 = c2 & (NTOK-1);
  float w1v = (s1 < ROWS_MAX) ? g_wgt[c1] : 0.f;
  float w2v = (s2 < ROWS_MAX) ? g_wgt[c2] : 0.f;
  size_t y1o = (s1 < ROWS_MAX) ? ((size_t)(c1>>13)*ROWS_MAX + s1)*EDIM : 0;
  size_t y2o = (s2 < ROWS_MAX) ? ((size_t)(c2>>13)*ROWS_MAX + s2)*EDIM : 0;
  const float4* xr = reinterpret_cast<const float4*>(x + (size_t)t*EDIM);
  const float4* y1 = reinterpret_cast<const float4*>(g_ybuf + y1o);
  const float4* y2 = reinterpret_cast<const float4*>(g_ybuf + y2o);
  float4* o = reinterpret_cast<float4*>(out + (size_t)t*EDIM);
  for (int j = threadIdx.x; j < EDIM/4; j += blockDim.x){
    float4 a = xr[j], b = y1[j], c = y2[j];
    float4 rr;
    rr.x = a.x + w1v*b.x + w2v*c.x;
    rr.y = a.y + w1v*b.y + w2v*c.y;
    rr.z = a.z + w1v*b.z + w2v*c.z;
    rr.w = a.w + w1v*b.w + w2v*c.w;
    o[j] = rr;
  }
}

// ---------------- launch ----------------
extern "C" void kernel_launch(void* const* d_in, const int* in_sizes, int n_in,
                              void* d_out, int out_size){
  const float* x  = (const float*)d_in[0];
  const float* gw = (const float*)d_in[1];
  const float* gb = (const float*)d_in[2];
  const float* tp = (const float*)d_in[3];
  const float* w1 = (const float*)d_in[4];
  const float* b1 = (const float*)d_in[5];
  const float* w2 = (const float*)d_in[6];
  const float* b2 = (const float*)d_in[7];
  float* out = (float*)d_out;

  cudaFuncSetAttribute(moe_gemm<1>, cudaFuncAttributeMaxDynamicSharedMemorySize, SMEM_TOTAL);
  cudaFuncSetAttribute(moe_gemm<2>, cudaFuncAttributeMaxDynamicSharedMemorySize, SMEM_TOTAL);

  convert_kernel<<<1024, 256>>>(w1, w2, x);           // idx 0 (also inits counters)
  router_kernel<<<NTOK/8, 256>>>(x, gw, gb, tp);      // idx 1
  capacity_kernel<<<NEXP, 256>>>();                   // idx 2
  dim3 grid(EDIM/128, NEXP*32);
  moe_gemm<1><<<grid, 256, SMEM_TOTAL>>>(b1);         // idx 3  <-- profiled
  moe_gemm<2><<<grid, 256, SMEM_TOTAL>>>(b2);         // idx 4
  aux_kernel<<<1, 32>>>(out, out_size);               // idx 5
  combine_kernel<<<NTOK, 256>>>(x, out);              // idx 6
}